// round 16
// baseline (speedup 1.0000x reference)
#include <cuda_runtime.h>
#include <cuda_fp16.h>
#include <cstdint>

#define N_NODES 50000
#define N_EDGES 600000
#define N_TOT   (N_NODES + N_EDGES)
#define N_GRAPHS 256
#define D 128
#define NLAYER 4
#define BN_EPS 1e-5f
#define NREP 8

// ---------------- scratch (device globals; zero-initialized at load) ----------------
__device__ float    g_h0[(size_t)N_NODES * D];      // z ping (atom emb first)
__device__ float    g_h1[(size_t)N_NODES * D];      // z pong
__device__ __half   g_Wh4[NLAYER * D * D];          // per-layer W [n][k] fp16
__device__ float    g_stats4[NLAYER * NREP * 2 * D];
__device__ float    g_pool[N_GRAPHS * D];
__device__ int      g_off[N_NODES + 1];             // MUST be zero on entry
__device__ int      g_cur[N_NODES];
__device__ int      g_adj[N_TOT];                   // plain src index
__device__ unsigned g_cnt[(size_t)N_NODES * 16];    // per-node edge-attr counts [f*3+v], zeroed in atomhist

__device__ __forceinline__ void mma_f16(float* c, const uint32_t* a, const uint32_t* b) {
    asm volatile(
        "mma.sync.aligned.m16n8k16.row.col.f32.f16.f16.f32 "
        "{%0,%1,%2,%3}, {%4,%5,%6,%7}, {%8,%9}, {%0,%1,%2,%3};"
        : "+f"(c[0]), "+f"(c[1]), "+f"(c[2]), "+f"(c[3])
        : "r"(a[0]), "r"(a[1]), "r"(a[2]), "r"(a[3]), "r"(b[0]), "r"(b[1]));
}

__device__ __forceinline__ void stats_read(int l, int c, float* s, float* q) {
    const float* base = g_stats4 + (size_t)l * NREP * 256;
    float ss = 0.f, qq = 0.f;
#pragma unroll
    for (int r = 0; r < NREP; r++) {
        ss += base[r * 256 + c];
        qq += base[r * 256 + 128 + c];
    }
    *s = ss; *q = qq;
}

// =============== 1. atom embedding (smem table) + histogram + zero cnt/stats/pool =========
#define AH_BLOCKS 782
__global__ __launch_bounds__(256) void k_atomhist(const int* __restrict__ x,
                                                  const float* __restrict__ aemb,
                                                  const int* __restrict__ e_dst) {
    __shared__ float tab[9 * 3 * D];   // 13.5KB: rows [f][v<3][:]
    int t = threadIdx.x;
    for (int i = t; i < 9 * 3 * D; i += 256) {
        int f = i / (3 * D), rem = i % (3 * D);
        int v = rem / D, d = rem % D;
        tab[i] = __ldg(&aemb[(size_t)(f * 120 + v) * D + d]);
    }
    __syncthreads();

    int gtid = blockIdx.x * 256 + t;
    const int nthr = AH_BLOCKS * 256;
    int gwid = gtid >> 5, lane = gtid & 31;
    const int nwarp = nthr >> 5;
    const float4* aemb4 = (const float4*)aemb;

    for (int node = gwid; node < N_NODES; node += nwarp) {
        const int* xi = x + (size_t)node * 9;
        float4 acc = make_float4(0.f, 0.f, 0.f, 0.f);
#pragma unroll
        for (int f = 0; f < 9; f++) {
            int v = __ldg(&xi[f]);
            float4 e;
            if ((unsigned)v < 3u)
                e = *(const float4*)&tab[(f * 3 + v) * D + lane * 4];
            else
                e = __ldg(&aemb4[(size_t)(f * 120 + v) * 32 + lane]);
            acc.x += e.x; acc.y += e.y; acc.z += e.z; acc.w += e.w;
        }
        ((float4*)g_h0)[(size_t)node * 32 + lane] = acc;
    }
    for (int e = gtid; e < N_EDGES; e += nthr) atomicAdd(&g_off[__ldg(&e_dst[e])], 1);
    for (int i = gtid; i < N_NODES * 16; i += nthr) g_cnt[i] = 0u;
    for (int i = gtid; i < NLAYER * NREP * 2 * D; i += nthr) g_stats4[i] = 0.f;
    for (int i = gtid; i < N_GRAPHS * D; i += nthr) g_pool[i] = 0.f;
}

// =============== 2. single-block scan (block 0) + W fp16 convert (other blocks) ===========
#define WT_BLOCKS (NLAYER * D * D / 1024)             /* 64 */
__global__ void k_scanprep(const float* __restrict__ W) {
    int b = blockIdx.x, t = threadIdx.x;              // 1024 threads
    if (b == 0) {
        __shared__ int sh[1024];
        int base = t * 49;
        int sum = 0;
        for (int i = 0; i < 49; i++) {
            int idx = base + i;
            if (idx < N_NODES) sum += g_off[idx] + 1;  // +1 self loop
        }
        sh[t] = sum;
        __syncthreads();
        for (int off = 1; off < 1024; off <<= 1) {
            int xv = (t >= off) ? sh[t - off] : 0;
            __syncthreads();
            sh[t] += xv;
            __syncthreads();
        }
        int run = sh[t] - sum;
        for (int i = 0; i < 49; i++) {
            int idx = base + i;
            if (idx < N_NODES) {
                int c = g_off[idx] + 1;
                g_off[idx] = run;
                g_cur[idx] = run;
                run += c;
            }
        }
        if (t == 1023) g_off[N_NODES] = run;           // == N_TOT
    } else {
        int e = (b - 1) * 1024 + t;                    // [l][n][k] direct convert
        g_Wh4[e] = __float2half(__ldg(&W[e]));
    }
}

// =============== 3. scatter edges into CSR + per-node attr counts ===============
__global__ void k_scatter(const int* __restrict__ e_src, const int* __restrict__ e_dst,
                          const int* __restrict__ ea) {
    int t = blockIdx.x * blockDim.x + threadIdx.x;
    if (t >= N_TOT) return;
    int d, s;
    if (t < N_EDGES) {
        s = __ldg(&e_src[t]);
        d = __ldg(&e_dst[t]);
        const int* a = ea + (size_t)t * 5;
#pragma unroll
        for (int f = 0; f < 5; f++) {
            unsigned v = min((unsigned)__ldg(&a[f]), 2u);
            atomicAdd(&g_cnt[(size_t)d * 16 + f * 3 + v], 1u);
        }
    } else {
        d = s = t - N_EDGES;   // self loop: handled as +1 on v=0 in gather
    }
    int pos = atomicAdd(&g_cur[d], 1);
    g_adj[pos] = s;
}

// =============== 4. FUSED layer: cnt-weighted bond emb + gather(+BN+ReLU) -> MMA ==========
#define SAH 136
#define SBH 136
#define AH_HALVES (64 * SAH)
#define BH_HALVES (128 * SBH)
#define FUSED_SMEM ((AH_HALVES + BH_HALVES) * 2)   /* 52224 B -> 4 CTAs/SM */
#define FUSED_BLOCKS ((N_NODES + 63) / 64)         /* 782 */

__global__ __launch_bounds__(256, 4) void k_fused(int l, const float* __restrict__ bemb,
                                                  const float* __restrict__ bn_g,
                                                  const float* __restrict__ bn_b) {
    extern __shared__ __half smh[];
    __half* Bh = smh;                                 // [128][136] W[n][k]
    __half* Ah = smh + BH_HALVES;                     // [64][136] aggregates [m][k]
    const uint32_t* Ahw = (const uint32_t*)Ah;
    const uint32_t* Bhw = (const uint32_t*)Bh;

    const float* hin = (l & 1) ? g_h1 : g_h0;
    float* zout = (l & 1) ? g_h0 : g_h1;

    int t = threadIdx.x;
    int wid = t >> 5, lane = t & 31;
    int row0 = blockIdx.x * 64;

    // ---- B tile load (overlaps with gather) ----
    const uint4* B4 = (const uint4*)(g_Wh4 + (size_t)l * D * D);
#pragma unroll
    for (int i = 0; i < 8; i++) {
        int idx = t + i * 256;
        int r = idx >> 4, q = idx & 15;
        *(uint4*)&Bh[r * SBH + q * 8] = __ldg(&B4[idx]);
    }

    // ---- BN constants ----
    float scx, scy, scz, scw, shx, shy, shz, shw, flo;
    if (l > 0) {
        flo = 0.f;
        const float* gg = bn_g + (l - 1) * D;
        const float* bb = bn_b + (l - 1) * D;
        int c0 = lane * 4;
        float sc[4], sh[4];
#pragma unroll
        for (int j = 0; j < 4; j++) {
            float s, q;
            stats_read(l - 1, c0 + j, &s, &q);
            float mu = s * (1.f / (float)N_NODES);
            float var = q * (1.f / (float)N_NODES) - mu * mu;
            float rstd = rsqrtf(fmaxf(var, 0.f) + BN_EPS);
            sc[j] = rstd * __ldg(&gg[c0 + j]);
            sh[j] = __ldg(&bb[c0 + j]) - mu * sc[j];
        }
        scx = sc[0]; scy = sc[1]; scz = sc[2]; scw = sc[3];
        shx = sh[0]; shy = sh[1]; shz = sh[2]; shw = sh[3];
    } else {
        scx = scy = scz = scw = 1.f;
        shx = shy = shz = shw = 0.f;
        flo = __int_as_float(0xff800000);   // identity on h0
    }

    // ---- gather: warp wid handles nodes row0 + wid*8 .. +7 ----
    const float4* h4 = (const float4*)hin;
    const float* bl = bemb + (size_t)l * 5 * 7 * D;
#pragma unroll 1
    for (int i = 0; i < 8; i++) {
        int r = wid * 8 + i;
        int node = row0 + r;
        float4 acc = make_float4(0.f, 0.f, 0.f, 0.f);
        if (node < N_NODES) {
            // bond-embedding term: sum_{f,v} cnt[f][v] * bemb[f][v]  (+1 on v=0 for self-loop)
            const uint4* cp = (const uint4*)(g_cnt + (size_t)node * 16);
            uint4 q0 = __ldg(cp), q1 = __ldg(cp + 1), q2 = __ldg(cp + 2), q3 = __ldg(cp + 3);
            unsigned cw[15] = {q0.x, q0.y, q0.z, q0.w, q1.x, q1.y, q1.z, q1.w,
                               q2.x, q2.y, q2.z, q2.w, q3.x, q3.y, q3.z};
#pragma unroll
            for (int fv = 0; fv < 15; fv++) {
                int f = fv / 3, v = fv % 3;
                float w = (float)cw[fv] + ((v == 0) ? 1.f : 0.f);
                float4 e = __ldg((const float4*)(bl + (size_t)(f * 7 + v) * D) + lane);
                acc.x += w * e.x; acc.y += w * e.y;
                acc.z += w * e.z; acc.w += w * e.w;
            }
            // neighbor gather (+ self loop in adj) with fused BN+ReLU
            int s = __ldg(&g_off[node]), e = __ldg(&g_off[node + 1]);
            int j = s;
            for (; j + 4 <= e; j += 4) {
                int p0 = __ldg(&g_adj[j]);
                int p1 = __ldg(&g_adj[j + 1]);
                int p2 = __ldg(&g_adj[j + 2]);
                int p3 = __ldg(&g_adj[j + 3]);
                float4 z0 = __ldcg(&h4[(size_t)p0 * 32 + lane]);
                float4 z1 = __ldcg(&h4[(size_t)p1 * 32 + lane]);
                float4 z2 = __ldcg(&h4[(size_t)p2 * 32 + lane]);
                float4 z3 = __ldcg(&h4[(size_t)p3 * 32 + lane]);
                acc.x += fmaxf(z0.x * scx + shx, flo) + fmaxf(z1.x * scx + shx, flo)
                       + fmaxf(z2.x * scx + shx, flo) + fmaxf(z3.x * scx + shx, flo);
                acc.y += fmaxf(z0.y * scy + shy, flo) + fmaxf(z1.y * scy + shy, flo)
                       + fmaxf(z2.y * scy + shy, flo) + fmaxf(z3.y * scy + shy, flo);
                acc.z += fmaxf(z0.z * scz + shz, flo) + fmaxf(z1.z * scz + shz, flo)
                       + fmaxf(z2.z * scz + shz, flo) + fmaxf(z3.z * scz + shz, flo);
                acc.w += fmaxf(z0.w * scw + shw, flo) + fmaxf(z1.w * scw + shw, flo)
                       + fmaxf(z2.w * scw + shw, flo) + fmaxf(z3.w * scw + shw, flo);
            }
            for (; j < e; j++) {
                int p = __ldg(&g_adj[j]);
                float4 z = __ldcg(&h4[(size_t)p * 32 + lane]);
                acc.x += fmaxf(z.x * scx + shx, flo);
                acc.y += fmaxf(z.y * scy + shy, flo);
                acc.z += fmaxf(z.z * scz + shz, flo);
                acc.w += fmaxf(z.w * scw + shw, flo);
            }
        }
        __half2 lo = __floats2half2_rn(acc.x, acc.y);
        __half2 hi = __floats2half2_rn(acc.z, acc.w);
        *(__half2*)&Ah[r * SAH + lane * 4]     = lo;
        *(__half2*)&Ah[r * SAH + lane * 4 + 2] = hi;
    }
    __syncthreads();

    // ---- MMA: 4x2 warp grid, each warp 16 rows x 64 cols ----
    int warpM = wid & 3, warpN = wid >> 2;
    int lr = lane >> 2, lc = lane & 3;

    float c[8][4];
#pragma unroll
    for (int nt = 0; nt < 8; nt++)
#pragma unroll
        for (int j = 0; j < 4; j++) c[nt][j] = 0.f;

#pragma unroll
    for (int kk = 0; kk < 8; kk++) {
        int kw = kk * 8;
        uint32_t a[4], b[8][2];
        int r = warpM * 16 + lr;
        a[0] = Ahw[r * (SAH / 2) + kw + lc];
        a[1] = Ahw[(r + 8) * (SAH / 2) + kw + lc];
        a[2] = Ahw[r * (SAH / 2) + kw + 4 + lc];
        a[3] = Ahw[(r + 8) * (SAH / 2) + kw + 4 + lc];
#pragma unroll
        for (int nt = 0; nt < 8; nt++) {
            int n = warpN * 64 + nt * 8 + lr;
            b[nt][0] = Bhw[n * (SBH / 2) + kw + lc];
            b[nt][1] = Bhw[n * (SBH / 2) + kw + 4 + lc];
        }
#pragma unroll
        for (int nt = 0; nt < 8; nt++)
            mma_f16(c[nt], a, b[nt]);
    }

    // ---- store z + stats ----
    int r0 = row0 + warpM * 16 + lr;
    bool rok0 = (r0 < N_NODES), rok1 = (r0 + 8 < N_NODES);
#pragma unroll
    for (int nt = 0; nt < 8; nt++) {
        int col = warpN * 64 + nt * 8 + lc * 2;
        if (rok0)
            *(float2*)&zout[(size_t)r0 * D + col] = make_float2(c[nt][0], c[nt][1]);
        if (rok1)
            *(float2*)&zout[(size_t)(r0 + 8) * D + col] = make_float2(c[nt][2], c[nt][3]);
    }
    float* stat = g_stats4 + ((size_t)l * NREP + (blockIdx.x & (NREP - 1))) * 256;
#pragma unroll
    for (int nt = 0; nt < 8; nt++) {
#pragma unroll
        for (int jj = 0; jj < 2; jj++) {
            float s = c[nt][jj] + c[nt][jj + 2];
            float q = c[nt][jj] * c[nt][jj] + c[nt][jj + 2] * c[nt][jj + 2];
            s += __shfl_down_sync(0xFFFFFFFFu, s, 16);
            q += __shfl_down_sync(0xFFFFFFFFu, q, 16);
            s += __shfl_down_sync(0xFFFFFFFFu, s, 8);
            q += __shfl_down_sync(0xFFFFFFFFu, q, 8);
            s += __shfl_down_sync(0xFFFFFFFFu, s, 4);
            q += __shfl_down_sync(0xFFFFFFFFu, q, 4);
            if (lane < 4) {
                int col = warpN * 64 + nt * 8 + lane * 2 + jj;
                atomicAdd(&stat[col], s);
                atomicAdd(&stat[128 + col], q);
            }
        }
    }
}

// =============== 5. pool: 4-way split per graph, final BN+ReLU, atomic accumulate =========
__global__ void k_pool(const int* __restrict__ batch, const float* __restrict__ bn_g,
                       const float* __restrict__ bn_b) {
    int g = blockIdx.x, part = blockIdx.y, t = threadIdx.x;
    int lo = 0, hi = N_NODES;
    while (lo < hi) { int m = (lo + hi) >> 1; if (__ldg(&batch[m]) < g) lo = m + 1; else hi = m; }
    int lo2 = lo, hi2 = N_NODES;
    while (lo2 < hi2) { int m = (lo2 + hi2) >> 1; if (__ldg(&batch[m]) < g + 1) lo2 = m + 1; else hi2 = m; }

    int cnt = lo2 - lo;
    int per = (cnt + 3) >> 2;
    int rs = lo + part * per;
    int re = min(rs + per, lo2);
    if (rs >= re) return;

    float s0, q0;
    stats_read(3, t, &s0, &q0);
    float mu = s0 / (float)N_NODES;
    float var = q0 / (float)N_NODES - mu * mu;
    float rstd = rsqrtf(fmaxf(var, 0.f) + BN_EPS);
    float sc = rstd * __ldg(&bn_g[3 * D + t]);
    float sh = __ldg(&bn_b[3 * D + t]) - mu * sc;

    float s = 0.f;
    for (int r = rs; r < re; r++) {
        float v = g_h0[(size_t)r * D + t];    // final z in g_h0 after 4 layers
        s += fmaxf(v * sc + sh, 0.f);
    }
    atomicAdd(&g_pool[g * D + t], s);
}

// =============== 6. MLP head + g_off re-zero ===============
__global__ void k_mlp(const int* __restrict__ batch,
                      const float* __restrict__ w1, const float* __restrict__ b1,
                      const float* __restrict__ w2, const float* __restrict__ b2,
                      float* __restrict__ out) {
    int g = blockIdx.x, j = threadIdx.x;   // 64 threads
    int lo = 0, hi = N_NODES;
    while (lo < hi) { int m = (lo + hi) >> 1; if (__ldg(&batch[m]) < g) lo = m + 1; else hi = m; }
    int lo2 = lo, hi2 = N_NODES;
    while (lo2 < hi2) { int m = (lo2 + hi2) >> 1; if (__ldg(&batch[m]) < g + 1) lo2 = m + 1; else hi2 = m; }
    float inv = 1.f / (float)max(lo2 - lo, 1);

    const float* gp = g_pool + g * D;
    const float* wr = w1 + j * D;
    float a = b1[j];
#pragma unroll 4
    for (int k = 0; k < D; k++) a += gp[k] * inv * wr[k];
    a = fmaxf(a, 0.f);
    float v = a * w2[j];
#pragma unroll
    for (int o = 16; o > 0; o >>= 1) v += __shfl_down_sync(0xFFFFFFFFu, v, o);
    __shared__ float sh[2];
    if ((j & 31) == 0) sh[j >> 5] = v;
    __syncthreads();
    if (j == 0) out[g] = sh[0] + sh[1] + b2[0];
    for (int i = g * 64 + j; i < N_NODES + 1; i += N_GRAPHS * 64) g_off[i] = 0;
}

// ---------------- launch ----------------
extern "C" void kernel_launch(void* const* d_in, const int* in_sizes, int n_in,
                              void* d_out, int out_size) {
    const int*   x        = (const int*)d_in[0];
    const int*   ei       = (const int*)d_in[1];
    const int*   ea       = (const int*)d_in[2];
    const int*   batch    = (const int*)d_in[3];
    const float* atom_emb = (const float*)d_in[4];
    const float* bond_emb = (const float*)d_in[5];
    const float* lin_w    = (const float*)d_in[6];
    const float* bn_g     = (const float*)d_in[8];
    const float* bn_b     = (const float*)d_in[9];
    const float* w1       = (const float*)d_in[10];
    const float* b1       = (const float*)d_in[11];
    const float* w2       = (const float*)d_in[12];
    const float* b2       = (const float*)d_in[13];
    float* out = (float*)d_out;

    const int* e_src = ei;
    const int* e_dst = ei + N_EDGES;

    cudaFuncSetAttribute(k_fused, cudaFuncAttributeMaxDynamicSharedMemorySize, FUSED_SMEM);

    k_atomhist<<<AH_BLOCKS, 256>>>(x, atom_emb, e_dst);                    // 0
    k_scanprep<<<1 + WT_BLOCKS, 1024>>>(lin_w);                            // 1
    k_scatter<<<(N_TOT + 255) / 256, 256>>>(e_src, e_dst, ea);             // 2

    for (int l = 0; l < NLAYER; l++)
        k_fused<<<FUSED_BLOCKS, 256, FUSED_SMEM>>>(l, bond_emb, bn_g, bn_b);  // 3 <- profiled

    dim3 poolgrid(N_GRAPHS, 4);
    k_pool<<<poolgrid, D>>>(batch, bn_g, bn_b);
    k_mlp<<<N_GRAPHS, 64>>>(batch, w1, b1, w2, b2, out);
}

// round 17
// speedup vs baseline: 1.1607x; 1.1607x over previous
#include <cuda_runtime.h>
#include <cuda_fp16.h>
#include <cstdint>

#define N_NODES 50000
#define N_EDGES 600000
#define N_TOT   (N_NODES + N_EDGES)
#define N_GRAPHS 256
#define D 128
#define NLAYER 4
#define BN_EPS 1e-5f
#define NREP 8

// ---------------- scratch (device globals; zero-initialized at load) ----------------
__device__ __half g_hh0[(size_t)N_NODES * D];     // fp16 h/z ping (atom emb first)
__device__ __half g_hh1[(size_t)N_NODES * D];     // fp16 h/z pong
__device__ __half g_Wh4[NLAYER * D * D];          // per-layer W [n][k] fp16
__device__ __half g_cth[NLAYER * 243 * D];        // per-layer combo bond tables, fp16
__device__ float  g_stats4[NLAYER * NREP * 2 * D];
__device__ float  g_pool[N_GRAPHS * D];
__device__ int    g_off[N_NODES + 1];             // MUST be zero on entry
__device__ int    g_cur[N_NODES];
__device__ int    g_adj[N_TOT];                   // packed: src | (combo<<16)

__device__ __forceinline__ void mma_f16(float* c, const uint32_t* a, const uint32_t* b) {
    asm volatile(
        "mma.sync.aligned.m16n8k16.row.col.f32.f16.f16.f32 "
        "{%0,%1,%2,%3}, {%4,%5,%6,%7}, {%8,%9}, {%0,%1,%2,%3};"
        : "+f"(c[0]), "+f"(c[1]), "+f"(c[2]), "+f"(c[3])
        : "r"(a[0]), "r"(a[1]), "r"(a[2]), "r"(a[3]), "r"(b[0]), "r"(b[1]));
}

__device__ __forceinline__ void stats_read(int l, int c, float* s, float* q) {
    const float* base = g_stats4 + (size_t)l * NREP * 256;
    float ss = 0.f, qq = 0.f;
#pragma unroll
    for (int r = 0; r < NREP; r++) {
        ss += base[r * 256 + c];
        qq += base[r * 256 + 128 + c];
    }
    *s = ss; *q = qq;
}

// =============== 1. atom embedding (fp16 out) + degree histogram + zero stats/pool ========
__global__ void k_atomhist(const int* __restrict__ x, const float* __restrict__ aemb,
                           const int* __restrict__ e_dst) {
    int gid = blockIdx.x * blockDim.x + threadIdx.x;
    int node = gid >> 5, lane = gid & 31;
    if (node < N_NODES) {
        const int* xi = x + (size_t)node * 9;
        float4 acc = make_float4(0.f, 0.f, 0.f, 0.f);
#pragma unroll
        for (int f = 0; f < 9; f++) {
            int v = __ldg(&xi[f]);
            float4 e = __ldg(&((const float4*)aemb)[(size_t)(f * 120 + v) * 32 + lane]);
            acc.x += e.x; acc.y += e.y; acc.z += e.z; acc.w += e.w;
        }
        __half2 lo = __floats2half2_rn(acc.x, acc.y);
        __half2 hi = __floats2half2_rn(acc.z, acc.w);
        ((uint2*)g_hh0)[(size_t)node * 32 + lane] =
            make_uint2(*(uint32_t*)&lo, *(uint32_t*)&hi);
    }
    if (gid < N_EDGES) atomicAdd(&g_off[__ldg(&e_dst[gid])], 1);
    if (gid < NLAYER * NREP * 2 * D) g_stats4[gid] = 0.f;
    if (gid < N_GRAPHS * D) g_pool[gid] = 0.f;
}

// =============== 2. single-block scan + ct fp16 tables + W fp16 convert ===============
#define CT_BLOCKS ((NLAYER * 243 + 7) / 8)            /* 122 */
#define WT_BLOCKS (NLAYER * D * D / 1024)             /* 64 */
__global__ void k_scanprep(const float* __restrict__ bemb, const float* __restrict__ W) {
    int b = blockIdx.x, t = threadIdx.x;              // 1024 threads
    if (b == 0) {
        __shared__ int sh[1024];
        int base = t * 49;
        int sum = 0;
        for (int i = 0; i < 49; i++) {
            int idx = base + i;
            if (idx < N_NODES) sum += g_off[idx] + 1;  // +1 self loop
        }
        sh[t] = sum;
        __syncthreads();
        for (int off = 1; off < 1024; off <<= 1) {
            int xv = (t >= off) ? sh[t - off] : 0;
            __syncthreads();
            sh[t] += xv;
            __syncthreads();
        }
        int run = sh[t] - sum;
        for (int i = 0; i < 49; i++) {
            int idx = base + i;
            if (idx < N_NODES) {
                int c = g_off[idx] + 1;
                g_off[idx] = run;
                g_cur[idx] = run;
                run += c;
            }
        }
        if (t == 1023) g_off[N_NODES] = run;           // == N_TOT
    } else if (b <= CT_BLOCKS) {
        int r = (b - 1) * 8 + (t >> 7);                // 0..971 = l*243 + combo
        int lane = t & 127;
        if (r < NLAYER * 243) {
            int l = r / 243, c = r % 243;
            const float* bl = bemb + (size_t)l * 5 * 7 * D;
            int cc = c;
            float acc = 0.f;
#pragma unroll
            for (int f = 0; f < 5; f++) {
                int dig = cc % 3; cc /= 3;
                acc += __ldg(&bl[(f * 7 + dig) * D + lane]);
            }
            g_cth[(size_t)r * D + lane] = __float2half(acc);
        }
    } else {
        int e = (b - 1 - CT_BLOCKS) * 1024 + t;        // [l][n][k] direct convert
        g_Wh4[e] = __float2half(__ldg(&W[e]));
    }
}

// =============== 3. scatter edges into CSR (packed src|combo) ===============
__global__ void k_scatter(const int* __restrict__ e_src, const int* __restrict__ e_dst,
                          const int* __restrict__ ea) {
    int t = blockIdx.x * blockDim.x + threadIdx.x;
    if (t >= N_TOT) return;
    int d, s, comb;
    if (t < N_EDGES) {
        s = __ldg(&e_src[t]);
        d = __ldg(&e_dst[t]);
        const int* a = ea + (size_t)t * 5;
        comb = a[0] + 3 * a[1] + 9 * a[2] + 27 * a[3] + 81 * a[4];
    } else {
        d = s = t - N_EDGES;
        comb = 0;
    }
    int pos = atomicAdd(&g_cur[d], 1);
    g_adj[pos] = s | (comb << 16);
}

// =============== 4. FUSED layer: fp16 gather(+BN+ReLU) -> smem A -> MMA -> fp16 z + stats ==
#define SAH 136
#define SBH 136
#define AH_HALVES (64 * SAH)
#define BH_HALVES (128 * SBH)
#define FUSED_SMEM ((AH_HALVES + BH_HALVES) * 2)   /* 52224 B -> 4 CTAs/SM */
#define FUSED_BLOCKS ((N_NODES + 63) / 64)         /* 782 */

__global__ __launch_bounds__(256, 4) void k_fused(int l, const float* __restrict__ bn_g,
                                                  const float* __restrict__ bn_b) {
    extern __shared__ __half smh[];
    __half* Bh = smh;                                 // [128][136] W[n][k]
    __half* Ah = smh + BH_HALVES;                     // [64][136] aggregates [m][k]
    const uint32_t* Ahw = (const uint32_t*)Ah;
    const uint32_t* Bhw = (const uint32_t*)Bh;

    const uint2* hin = (l & 1) ? (const uint2*)g_hh1 : (const uint2*)g_hh0;
    __half* hout = (l & 1) ? g_hh0 : g_hh1;

    int t = threadIdx.x;
    int wid = t >> 5, lane = t & 31;
    int row0 = blockIdx.x * 64;

    // ---- B tile load (overlaps with gather) ----
    const uint4* B4 = (const uint4*)(g_Wh4 + (size_t)l * D * D);
#pragma unroll
    for (int i = 0; i < 8; i++) {
        int idx = t + i * 256;
        int r = idx >> 4, q = idx & 15;
        *(uint4*)&Bh[r * SBH + q * 8] = __ldg(&B4[idx]);
    }

    // ---- BN constants for this thread's 4 columns ----
    float scx, scy, scz, scw, shx, shy, shz, shw, flo;
    if (l > 0) {
        flo = 0.f;
        const float* gg = bn_g + (l - 1) * D;
        const float* bb = bn_b + (l - 1) * D;
        int c0 = lane * 4;
        float sc[4], sh[4];
#pragma unroll
        for (int j = 0; j < 4; j++) {
            float s, q;
            stats_read(l - 1, c0 + j, &s, &q);
            float mu = s * (1.f / (float)N_NODES);
            float var = q * (1.f / (float)N_NODES) - mu * mu;
            float rstd = rsqrtf(fmaxf(var, 0.f) + BN_EPS);
            sc[j] = rstd * __ldg(&gg[c0 + j]);
            sh[j] = __ldg(&bb[c0 + j]) - mu * sc[j];
        }
        scx = sc[0]; scy = sc[1]; scz = sc[2]; scw = sc[3];
        shx = sh[0]; shy = sh[1]; shz = sh[2]; shw = sh[3];
    } else {
        scx = scy = scz = scw = 1.f;
        shx = shy = shz = shw = 0.f;
        flo = __int_as_float(0xff800000);   // -inf: identity on h0
    }

    // ---- gather: warp wid aggregates nodes row0 + wid*8 .. +7 into Ah (fp16) ----
    const uint2* ct2 = (const uint2*)(g_cth + (size_t)l * 243 * D);
#pragma unroll 1
    for (int i = 0; i < 8; i++) {
        int r = wid * 8 + i;
        int node = row0 + r;
        float4 acc = make_float4(0.f, 0.f, 0.f, 0.f);
        if (node < N_NODES) {
            int s = __ldg(&g_off[node]), e = __ldg(&g_off[node + 1]);
            int j = s;
            for (; j + 4 <= e; j += 4) {
                int p0 = __ldg(&g_adj[j]);
                int p1 = __ldg(&g_adj[j + 1]);
                int p2 = __ldg(&g_adj[j + 2]);
                int p3 = __ldg(&g_adj[j + 3]);
                uint2 zz0 = __ldcg(&hin[(size_t)(p0 & 0xFFFF) * 32 + lane]);
                uint2 zz1 = __ldcg(&hin[(size_t)(p1 & 0xFFFF) * 32 + lane]);
                uint2 zz2 = __ldcg(&hin[(size_t)(p2 & 0xFFFF) * 32 + lane]);
                uint2 zz3 = __ldcg(&hin[(size_t)(p3 & 0xFFFF) * 32 + lane]);
                uint2 cc0 = __ldg(&ct2[(p0 >> 16) * 32 + lane]);
                uint2 cc1 = __ldg(&ct2[(p1 >> 16) * 32 + lane]);
                uint2 cc2 = __ldg(&ct2[(p2 >> 16) * 32 + lane]);
                uint2 cc3 = __ldg(&ct2[(p3 >> 16) * 32 + lane]);
#pragma unroll
                for (int u = 0; u < 4; u++) {
                    uint2 zz = (u == 0) ? zz0 : (u == 1) ? zz1 : (u == 2) ? zz2 : zz3;
                    uint2 cc = (u == 0) ? cc0 : (u == 1) ? cc1 : (u == 2) ? cc2 : cc3;
                    float2 za = __half22float2(*(__half2*)&zz.x);
                    float2 zb = __half22float2(*(__half2*)&zz.y);
                    float2 ca = __half22float2(*(__half2*)&cc.x);
                    float2 cb = __half22float2(*(__half2*)&cc.y);
                    acc.x += fmaxf(za.x * scx + shx, flo) + ca.x;
                    acc.y += fmaxf(za.y * scy + shy, flo) + ca.y;
                    acc.z += fmaxf(zb.x * scz + shz, flo) + cb.x;
                    acc.w += fmaxf(zb.y * scw + shw, flo) + cb.y;
                }
            }
            for (; j < e; j++) {
                int p = __ldg(&g_adj[j]);
                uint2 zz = __ldcg(&hin[(size_t)(p & 0xFFFF) * 32 + lane]);
                uint2 cc = __ldg(&ct2[(p >> 16) * 32 + lane]);
                float2 za = __half22float2(*(__half2*)&zz.x);
                float2 zb = __half22float2(*(__half2*)&zz.y);
                float2 ca = __half22float2(*(__half2*)&cc.x);
                float2 cb = __half22float2(*(__half2*)&cc.y);
                acc.x += fmaxf(za.x * scx + shx, flo) + ca.x;
                acc.y += fmaxf(za.y * scy + shy, flo) + ca.y;
                acc.z += fmaxf(zb.x * scz + shz, flo) + cb.x;
                acc.w += fmaxf(zb.y * scw + shw, flo) + cb.y;
            }
        }
        __half2 lo = __floats2half2_rn(acc.x, acc.y);
        __half2 hi = __floats2half2_rn(acc.z, acc.w);
        *(__half2*)&Ah[r * SAH + lane * 4]     = lo;
        *(__half2*)&Ah[r * SAH + lane * 4 + 2] = hi;
    }
    __syncthreads();

    // ---- MMA: 4x2 warp grid, each warp 16 rows x 64 cols (validated layout) ----
    int warpM = wid & 3, warpN = wid >> 2;
    int lr = lane >> 2, lc = lane & 3;

    float c[8][4];
#pragma unroll
    for (int nt = 0; nt < 8; nt++)
#pragma unroll
        for (int j = 0; j < 4; j++) c[nt][j] = 0.f;

#pragma unroll
    for (int kk = 0; kk < 8; kk++) {
        int kw = kk * 8;
        uint32_t a[4], b[8][2];
        int r = warpM * 16 + lr;
        a[0] = Ahw[r * (SAH / 2) + kw + lc];
        a[1] = Ahw[(r + 8) * (SAH / 2) + kw + lc];
        a[2] = Ahw[r * (SAH / 2) + kw + 4 + lc];
        a[3] = Ahw[(r + 8) * (SAH / 2) + kw + 4 + lc];
#pragma unroll
        for (int nt = 0; nt < 8; nt++) {
            int n = warpN * 64 + nt * 8 + lr;
            b[nt][0] = Bhw[n * (SBH / 2) + kw + lc];
            b[nt][1] = Bhw[n * (SBH / 2) + kw + 4 + lc];
        }
#pragma unroll
        for (int nt = 0; nt < 8; nt++)
            mma_f16(c[nt], a, b[nt]);
    }

    // ---- store z (fp16) + stats (fp32 exact, padded rows contribute 0) ----
    int r0 = row0 + warpM * 16 + lr;
    bool rok0 = (r0 < N_NODES), rok1 = (r0 + 8 < N_NODES);
#pragma unroll
    for (int nt = 0; nt < 8; nt++) {
        int col = warpN * 64 + nt * 8 + lc * 2;
        if (rok0) {
            __half2 v = __floats2half2_rn(c[nt][0], c[nt][1]);
            *(__half2*)&hout[(size_t)r0 * D + col] = v;
        }
        if (rok1) {
            __half2 v = __floats2half2_rn(c[nt][2], c[nt][3]);
            *(__half2*)&hout[(size_t)(r0 + 8) * D + col] = v;
        }
    }
    float* stat = g_stats4 + ((size_t)l * NREP + (blockIdx.x & (NREP - 1))) * 256;
#pragma unroll
    for (int nt = 0; nt < 8; nt++) {
#pragma unroll
        for (int jj = 0; jj < 2; jj++) {
            float s = c[nt][jj] + c[nt][jj + 2];
            float q = c[nt][jj] * c[nt][jj] + c[nt][jj + 2] * c[nt][jj + 2];
            s += __shfl_down_sync(0xFFFFFFFFu, s, 16);
            q += __shfl_down_sync(0xFFFFFFFFu, q, 16);
            s += __shfl_down_sync(0xFFFFFFFFu, s, 8);
            q += __shfl_down_sync(0xFFFFFFFFu, q, 8);
            s += __shfl_down_sync(0xFFFFFFFFu, s, 4);
            q += __shfl_down_sync(0xFFFFFFFFu, q, 4);
            if (lane < 4) {
                int col = warpN * 64 + nt * 8 + lane * 2 + jj;
                atomicAdd(&stat[col], s);
                atomicAdd(&stat[128 + col], q);
            }
        }
    }
}

// =============== 5. pool: 4-way split per graph, fp16 z3 + final BN+ReLU ===============
__global__ void k_pool(const int* __restrict__ batch, const float* __restrict__ bn_g,
                       const float* __restrict__ bn_b) {
    int g = blockIdx.x, part = blockIdx.y, t = threadIdx.x;
    int lo = 0, hi = N_NODES;
    while (lo < hi) { int m = (lo + hi) >> 1; if (__ldg(&batch[m]) < g) lo = m + 1; else hi = m; }
    int lo2 = lo, hi2 = N_NODES;
    while (lo2 < hi2) { int m = (lo2 + hi2) >> 1; if (__ldg(&batch[m]) < g + 1) lo2 = m + 1; else hi2 = m; }

    int cnt = lo2 - lo;
    int per = (cnt + 3) >> 2;
    int rs = lo + part * per;
    int re = min(rs + per, lo2);
    if (rs >= re) return;

    float s0, q0;
    stats_read(3, t, &s0, &q0);
    float mu = s0 / (float)N_NODES;
    float var = q0 / (float)N_NODES - mu * mu;
    float rstd = rsqrtf(fmaxf(var, 0.f) + BN_EPS);
    float sc = rstd * __ldg(&bn_g[3 * D + t]);
    float sh = __ldg(&bn_b[3 * D + t]) - mu * sc;

    float s = 0.f;
    for (int r = rs; r < re; r++) {
        float v = __half2float(g_hh0[(size_t)r * D + t]);   // final z in g_hh0
        s += fmaxf(v * sc + sh, 0.f);
    }
    atomicAdd(&g_pool[g * D + t], s);
}

// =============== 6. MLP head + g_off re-zero ===============
__global__ void k_mlp(const int* __restrict__ batch,
                      const float* __restrict__ w1, const float* __restrict__ b1,
                      const float* __restrict__ w2, const float* __restrict__ b2,
                      float* __restrict__ out) {
    int g = blockIdx.x, j = threadIdx.x;   // 64 threads
    int lo = 0, hi = N_NODES;
    while (lo < hi) { int m = (lo + hi) >> 1; if (__ldg(&batch[m]) < g) lo = m + 1; else hi = m; }
    int lo2 = lo, hi2 = N_NODES;
    while (lo2 < hi2) { int m = (lo2 + hi2) >> 1; if (__ldg(&batch[m]) < g + 1) lo2 = m + 1; else hi2 = m; }
    float inv = 1.f / (float)max(lo2 - lo, 1);

    const float* gp = g_pool + g * D;
    const float* wr = w1 + j * D;
    float a = b1[j];
#pragma unroll 4
    for (int k = 0; k < D; k++) a += gp[k] * inv * wr[k];
    a = fmaxf(a, 0.f);
    float v = a * w2[j];
#pragma unroll
    for (int o = 16; o > 0; o >>= 1) v += __shfl_down_sync(0xFFFFFFFFu, v, o);
    __shared__ float sh[2];
    if ((j & 31) == 0) sh[j >> 5] = v;
    __syncthreads();
    if (j == 0) out[g] = sh[0] + sh[1] + b2[0];
    for (int i = g * 64 + j; i < N_NODES + 1; i += N_GRAPHS * 64) g_off[i] = 0;
}

// ---------------- launch ----------------
extern "C" void kernel_launch(void* const* d_in, const int* in_sizes, int n_in,
                              void* d_out, int out_size) {
    const int*   x        = (const int*)d_in[0];
    const int*   ei       = (const int*)d_in[1];
    const int*   ea       = (const int*)d_in[2];
    const int*   batch    = (const int*)d_in[3];
    const float* atom_emb = (const float*)d_in[4];
    const float* bond_emb = (const float*)d_in[5];
    const float* lin_w    = (const float*)d_in[6];
    const float* bn_g     = (const float*)d_in[8];
    const float* bn_b     = (const float*)d_in[9];
    const float* w1       = (const float*)d_in[10];
    const float* b1       = (const float*)d_in[11];
    const float* w2       = (const float*)d_in[12];
    const float* b2       = (const float*)d_in[13];
    float* out = (float*)d_out;

    const int* e_src = ei;
    const int* e_dst = ei + N_EDGES;

    cudaFuncSetAttribute(k_fused, cudaFuncAttributeMaxDynamicSharedMemorySize, FUSED_SMEM);

    k_atomhist<<<(N_NODES * 32 + 255) / 256, 256>>>(x, atom_emb, e_dst);   // 0
    k_scanprep<<<1 + CT_BLOCKS + WT_BLOCKS, 1024>>>(bond_emb, lin_w);      // 1
    k_scatter<<<(N_TOT + 255) / 256, 256>>>(e_src, e_dst, ea);             // 2

    for (int l = 0; l < NLAYER; l++)
        k_fused<<<FUSED_BLOCKS, 256, FUSED_SMEM>>>(l, bn_g, bn_b);         // 3 <- profiled (l=0)

    dim3 poolgrid(N_GRAPHS, 4);
    k_pool<<<poolgrid, D>>>(batch, bn_g, bn_b);
    k_mlp<<<N_GRAPHS, 64>>>(batch, w1, b1, w2, b2, out);
}